// round 2
// baseline (speedup 1.0000x reference)
#include <cuda_runtime.h>
#include <cuda_fp16.h>

#define NV 50000
#define NE 1250000
#define DD 64

// ---------------- scratch (device globals: no runtime allocation allowed) ----
__device__ float  g_h[(size_t)NV * DD];        // node projection h = nf@Wn + bn
__device__ __half g_msg[(size_t)NE * DD];      // messages, stored in dst-sorted (CSR) order
__device__ int    g_rank[NE];                  // rank of edge within its dst bucket
__device__ int    g_cnt[NV];                   // histogram
__device__ int    g_off[NV + 1];               // CSR offsets
__device__ int    g_bsum[64];                  // scan block sums

// ---------------- helpers ---------------------------------------------------
__device__ __forceinline__ float sspf(float x) {
    // shifted softplus: log(1+e^x) - log(2), numerically stable
    return fmaxf(x, 0.f) + log1pf(expf(-fabsf(x))) - 0.69314718055994531f;
}
__device__ __forceinline__ unsigned f2tf32(float x) {
    unsigned r;
    asm("cvt.rna.tf32.f32 %0, %1;" : "=r"(r) : "f"(x));
    return r;
}
__device__ __forceinline__ void mma_tf32(float c[4], unsigned a0, unsigned a1,
                                         unsigned a2, unsigned a3,
                                         unsigned b0, unsigned b1) {
    asm("mma.sync.aligned.m16n8k8.row.col.f32.tf32.tf32.f32 "
        "{%0,%1,%2,%3}, {%4,%5,%6,%7}, {%8,%9}, {%0,%1,%2,%3};"
        : "+f"(c[0]), "+f"(c[1]), "+f"(c[2]), "+f"(c[3])
        : "r"(a0), "r"(a1), "r"(a2), "r"(a3), "r"(b0), "r"(b1));
}

// Pack a 64x64 row-major W into per-lane mma B-fragment order (tf32-converted):
// Wp[((ks*8+nt)*32 + lane)*2 + j] = tf32(W[(ks*8 + tig + j*4) * 64 + nt*8 + gid])
__device__ __forceinline__ void packW(const float* __restrict__ W, unsigned* Wp,
                                      int tid, int nthr) {
    for (int idx = tid; idx < 4096; idx += nthr) {
        int j    = idx & 1;
        int lane = (idx >> 1) & 31;
        int nt   = (idx >> 6) & 7;
        int ks   = idx >> 9;
        int g = lane >> 2, t4 = lane & 3;
        int k = ks * 8 + t4 + j * 4;
        int n = nt * 8 + g;
        Wp[idx] = f2tf32(W[k * DD + n]);
    }
}

// [128,64] @ [64,64] per block, 8 warps x 16 rows, acc[nt][0..3] per thread.
__device__ __forceinline__ void gemm_tile(const float (*As)[68],
                                          const unsigned* __restrict__ Wp,
                                          float acc[8][4], int wr, int gid, int tig) {
    #pragma unroll
    for (int ks = 0; ks < 8; ks++) {
        unsigned a0 = f2tf32(As[wr + gid    ][ks * 8 + tig]);
        unsigned a1 = f2tf32(As[wr + gid + 8][ks * 8 + tig]);
        unsigned a2 = f2tf32(As[wr + gid    ][ks * 8 + tig + 4]);
        unsigned a3 = f2tf32(As[wr + gid + 8][ks * 8 + tig + 4]);
        #pragma unroll
        for (int nt = 0; nt < 8; nt++) {
            uint2 b = ((const uint2*)Wp)[(ks * 8 + nt) * 32 + (gid * 4 + tig)];
            mma_tf32(acc[nt], a0, a1, a2, a3, b.x, b.y);
        }
    }
}

// ---------------- CSR build -------------------------------------------------
__global__ void zero_cnt_kernel() {
    int i = blockIdx.x * blockDim.x + threadIdx.x;
    if (i < NV) g_cnt[i] = 0;
}
__global__ void hist_kernel(const int* __restrict__ dst) {
    int e = blockIdx.x * blockDim.x + threadIdx.x;
    if (e < NE) g_rank[e] = atomicAdd(&g_cnt[dst[e]], 1);
}
__global__ void scan1_kernel() {
    __shared__ int ws[32];
    int t = threadIdx.x, b = blockIdx.x;
    int i = b * 1024 + t;
    int x = (i < NV) ? g_cnt[i] : 0;
    int incl = x;
    #pragma unroll
    for (int o = 1; o < 32; o <<= 1) {
        int n = __shfl_up_sync(0xffffffffu, incl, o);
        if ((t & 31) >= o) incl += n;
    }
    if ((t & 31) == 31) ws[t >> 5] = incl;
    __syncthreads();
    if (t < 32) {
        int v = ws[t];
        int iv = v;
        #pragma unroll
        for (int o = 1; o < 32; o <<= 1) {
            int n = __shfl_up_sync(0xffffffffu, iv, o);
            if (t >= o) iv += n;
        }
        ws[t] = iv - v;  // exclusive warp prefix
    }
    __syncthreads();
    int excl = ws[t >> 5] + incl - x;
    if (i < NV) g_off[i] = excl;
    if (t == 1023) g_bsum[b] = excl + x;
}
__global__ void scan2_kernel() {
    int run = 0;
    const int nb = (NV + 1023) / 1024;
    for (int b = 0; b < nb; b++) {
        int v = g_bsum[b];
        g_bsum[b] = run;
        run += v;
    }
}
__global__ void scan3_kernel() {
    int t = threadIdx.x, b = blockIdx.x;
    int i = b * 1024 + t;
    if (i < NV) g_off[i] += g_bsum[b];
    if (i == 0) g_off[NV] = NE;
}

// ---------------- h = node_feats @ Wn + bn ----------------------------------
struct HSmem {
    float As[128][68];
    unsigned Wp[4096];
    float bs[64];
};
__global__ void __launch_bounds__(256, 2)
h_kernel(const float* __restrict__ nf, const float* __restrict__ Wn,
         const float* __restrict__ bn) {
    extern __shared__ char smraw[];
    HSmem& sm = *reinterpret_cast<HSmem*>(smraw);
    int tid = threadIdx.x, lane = tid & 31, warp = tid >> 5;
    int gid = lane >> 2, tig = lane & 3, wr = warp * 16;
    packW(Wn, sm.Wp, tid, 256);
    if (tid < 64) sm.bs[tid] = bn[tid];
    int base = blockIdx.x * 128;
    int rows = min(128, NV - base);
    #pragma unroll
    for (int j = 0; j < 8; j++) {
        int f4 = tid + j * 256;
        int r = f4 >> 4, c4 = f4 & 15;
        float4 v = (r < rows) ? ((const float4*)(nf + (size_t)(base + r) * DD))[c4]
                              : make_float4(0.f, 0.f, 0.f, 0.f);
        *(float4*)&sm.As[r][c4 * 4] = v;
    }
    __syncthreads();
    float acc[8][4];
    #pragma unroll
    for (int i = 0; i < 8; i++)
        #pragma unroll
        for (int j = 0; j < 4; j++) acc[i][j] = 0.f;
    gemm_tile(sm.As, sm.Wp, acc, wr, gid, tig);
    #pragma unroll
    for (int nt = 0; nt < 8; nt++) {
        int c0 = nt * 8 + tig * 2;
        float b0 = sm.bs[c0], b1 = sm.bs[c0 + 1];
        int r0 = wr + gid, r1 = wr + gid + 8;
        if (r0 < rows) {
            float2 v = make_float2(acc[nt][0] + b0, acc[nt][1] + b1);
            *(float2*)(g_h + (size_t)(base + r0) * DD + c0) = v;
        }
        if (r1 < rows) {
            float2 v = make_float2(acc[nt][2] + b0, acc[nt][3] + b1);
            *(float2*)(g_h + (size_t)(base + r1) * DD + c0) = v;
        }
    }
}

// ---------------- edge kernel: MLP + gather-modulate + CSR scatter-write ----
struct EdgeSmem {
    float As[128][68];     // edge tile / intermediate / (reused) fp16 msg staging
    float Hs[128][68];     // gathered h rows
    unsigned Wp1[4096];
    unsigned Wp2[4096];
    float b1s[64], b2s[64];
    int srcS[128];
    int slotS[128];
};
__global__ void __launch_bounds__(256, 2)
edge_kernel(const float* __restrict__ ef, const int* __restrict__ src,
            const int* __restrict__ dst, const float* __restrict__ We1,
            const float* __restrict__ be1, const float* __restrict__ We2,
            const float* __restrict__ be2) {
    extern __shared__ char smraw[];
    EdgeSmem& sm = *reinterpret_cast<EdgeSmem*>(smraw);
    const int tid = threadIdx.x, lane = tid & 31, warp = tid >> 5;
    const int gid = lane >> 2, tig = lane & 3, wr = warp * 16;

    packW(We1, sm.Wp1, tid, 256);
    packW(We2, sm.Wp2, tid, 256);
    if (tid < 64) { sm.b1s[tid] = be1[tid]; sm.b2s[tid] = be2[tid]; }

    const int numTiles = (NE + 127) / 128;
    for (int tile = blockIdx.x; tile < numTiles; tile += gridDim.x) {
        const int base = tile * 128;
        const int rows = min(128, NE - base);
        __syncthreads();  // prev-iter readers done; Wp ready (first iter)

        if (tid < 128) {
            int r = tid;
            if (r < rows) {
                sm.srcS[r]  = src[base + r];
                sm.slotS[r] = g_off[dst[base + r]] + g_rank[base + r];
            }
        }
        #pragma unroll
        for (int j = 0; j < 8; j++) {
            int f4 = tid + j * 256;
            int r = f4 >> 4, c4 = f4 & 15;
            float4 v = (r < rows)
                           ? ((const float4*)(ef + (size_t)(base + r) * DD))[c4]
                           : make_float4(0.f, 0.f, 0.f, 0.f);
            *(float4*)&sm.As[r][c4 * 4] = v;
        }
        __syncthreads();

        // gather h[src] rows (random 256B reads, mostly L2 hits; hidden by MMA)
        #pragma unroll
        for (int j = 0; j < 8; j++) {
            int f4 = tid + j * 256;
            int r = f4 >> 4, c4 = f4 & 15;
            if (r < rows) {
                int s = sm.srcS[r];
                *(float4*)&sm.Hs[r][c4 * 4] =
                    ((const float4*)(g_h + (size_t)s * DD))[c4];
            }
        }

        float acc[8][4];
        #pragma unroll
        for (int i = 0; i < 8; i++)
            #pragma unroll
            for (int j = 0; j < 4; j++) acc[i][j] = 0.f;
        gemm_tile(sm.As, sm.Wp1, acc, wr, gid, tig);
        __syncthreads();

        // ssp(x + b1) -> back into As
        #pragma unroll
        for (int nt = 0; nt < 8; nt++) {
            int c0 = nt * 8 + tig * 2;
            float b0 = sm.b1s[c0], b1 = sm.b1s[c0 + 1];
            sm.As[wr + gid    ][c0]     = sspf(acc[nt][0] + b0);
            sm.As[wr + gid    ][c0 + 1] = sspf(acc[nt][1] + b1);
            sm.As[wr + gid + 8][c0]     = sspf(acc[nt][2] + b0);
            sm.As[wr + gid + 8][c0 + 1] = sspf(acc[nt][3] + b1);
        }
        __syncthreads();

        #pragma unroll
        for (int i = 0; i < 8; i++)
            #pragma unroll
            for (int j = 0; j < 4; j++) acc[i][j] = 0.f;
        gemm_tile(sm.As, sm.Wp2, acc, wr, gid, tig);
        __syncthreads();  // all warps done reading As before staging msg in it

        // f = ssp(x + b2); msg = f * h; stage as fp16, stride 72 halves
        __half* MsgS = (__half*)&sm.As[0][0];
        #pragma unroll
        for (int nt = 0; nt < 8; nt++) {
            int c0 = nt * 8 + tig * 2;
            float b0 = sm.b2s[c0], b1 = sm.b2s[c0 + 1];
            float2 h0 = *(const float2*)&sm.Hs[wr + gid    ][c0];
            float2 h1 = *(const float2*)&sm.Hs[wr + gid + 8][c0];
            float m0 = sspf(acc[nt][0] + b0) * h0.x;
            float m1 = sspf(acc[nt][1] + b1) * h0.y;
            float m2 = sspf(acc[nt][2] + b0) * h1.x;
            float m3 = sspf(acc[nt][3] + b1) * h1.y;
            *(__half2*)&MsgS[(wr + gid    ) * 72 + c0] = __floats2half2_rn(m0, m1);
            *(__half2*)&MsgS[(wr + gid + 8) * 72 + c0] = __floats2half2_rn(m2, m3);
        }
        __syncthreads();

        // scatter whole 128B rows to their CSR slot (coalesced 64B per thread)
        {
            int r = tid >> 1, part = tid & 1;
            if (r < rows) {
                int slot = sm.slotS[r];
                const uint4* sp = (const uint4*)&MsgS[r * 72 + part * 32];
                uint4* dp = (uint4*)(g_msg + (size_t)slot * DD + part * 32);
                #pragma unroll
                for (int i = 0; i < 4; i++) dp[i] = sp[i];
            }
        }
    }
}

// ---------------- node kernel: segment-sum + ssp(agg@Wc+bc)@Wo+bo -----------
struct NodeSmem {
    float Wc[64][64];
    float Wo[64][64];
    float agg[16][64];
    float bcs[64], bos[64];
};
__global__ void __launch_bounds__(512, 2)
node_kernel(const float* __restrict__ Wc, const float* __restrict__ bc,
            const float* __restrict__ Wo, const float* __restrict__ bo,
            float* __restrict__ out) {
    extern __shared__ char smraw[];
    NodeSmem& sm = *reinterpret_cast<NodeSmem*>(smraw);
    int tid = threadIdx.x, lane = tid & 31, warp = tid >> 5;  // 16 warps
    for (int i = tid; i < 4096; i += 512) ((float*)sm.Wc)[i] = Wc[i];
    for (int i = tid; i < 4096; i += 512) ((float*)sm.Wo)[i] = Wo[i];
    if (tid < 64) { sm.bcs[tid] = bc[tid]; sm.bos[tid] = bo[tid]; }
    __syncthreads();

    int v = blockIdx.x * 16 + warp;  // NV = 3125*16 exactly
    int s0 = g_off[v], s1 = g_off[v + 1];
    float a0 = 0.f, a1 = 0.f;  // cols 2*lane, 2*lane+1
    const unsigned* mp = (const unsigned*)g_msg;
    for (int s = s0; s < s1; s++) {
        unsigned u = mp[(size_t)s * 32 + lane];  // 128B coalesced per warp
        float2 f = __half22float2(*(__half2*)&u);
        a0 += f.x;
        a1 += f.y;
    }
    sm.agg[warp][2 * lane]     = a0;
    sm.agg[warp][2 * lane + 1] = a1;
    __syncwarp();

    float o0 = sm.bcs[2 * lane], o1 = sm.bcs[2 * lane + 1];
    #pragma unroll 8
    for (int k = 0; k < 64; k++) {
        float av = sm.agg[warp][k];
        float2 w = *(const float2*)&sm.Wc[k][2 * lane];
        o0 += av * w.x;
        o1 += av * w.y;
    }
    o0 = sspf(o0);
    o1 = sspf(o1);
    __syncwarp();
    sm.agg[warp][2 * lane]     = o0;
    sm.agg[warp][2 * lane + 1] = o1;
    __syncwarp();

    float r0 = sm.bos[2 * lane], r1 = sm.bos[2 * lane + 1];
    #pragma unroll 8
    for (int k = 0; k < 64; k++) {
        float tv = sm.agg[warp][k];
        float2 w = *(const float2*)&sm.Wo[k][2 * lane];
        r0 += tv * w.x;
        r1 += tv * w.y;
    }
    float2 res = make_float2(r0, r1);
    *(float2*)(out + (size_t)v * DD + 2 * lane) = res;
}

// ---------------- launch ----------------------------------------------------
extern "C" void kernel_launch(void* const* d_in, const int* in_sizes, int n_in,
                              void* d_out, int out_size) {
    const float* nf  = (const float*)d_in[0];
    const float* ef  = (const float*)d_in[1];
    const int*   src = (const int*)d_in[2];
    const int*   dst = (const int*)d_in[3];
    const float* We1 = (const float*)d_in[4];
    const float* be1 = (const float*)d_in[5];
    const float* We2 = (const float*)d_in[6];
    const float* be2 = (const float*)d_in[7];
    const float* Wn  = (const float*)d_in[8];
    const float* bn  = (const float*)d_in[9];
    const float* Wc  = (const float*)d_in[10];
    const float* bc  = (const float*)d_in[11];
    const float* Wo  = (const float*)d_in[12];
    const float* bo  = (const float*)d_in[13];
    float* out = (float*)d_out;

    cudaFuncSetAttribute(edge_kernel, cudaFuncAttributeMaxDynamicSharedMemorySize,
                         (int)sizeof(EdgeSmem));
    cudaFuncSetAttribute(h_kernel, cudaFuncAttributeMaxDynamicSharedMemorySize,
                         (int)sizeof(HSmem));
    cudaFuncSetAttribute(node_kernel, cudaFuncAttributeMaxDynamicSharedMemorySize,
                         (int)sizeof(NodeSmem));

    const int scanBlocks = (NV + 1023) / 1024;  // 49
    zero_cnt_kernel<<<scanBlocks, 1024>>>();
    hist_kernel<<<(NE + 255) / 256, 256>>>(dst);
    scan1_kernel<<<scanBlocks, 1024>>>();
    scan2_kernel<<<1, 1>>>();
    scan3_kernel<<<scanBlocks, 1024>>>();
    h_kernel<<<(NV + 127) / 128, 256, sizeof(HSmem)>>>(nf, Wn, bn);
    edge_kernel<<<296, 256, sizeof(EdgeSmem)>>>(ef, src, dst, We1, be1, We2, be2);
    node_kernel<<<NV / 16, 512, sizeof(NodeSmem)>>>(Wc, bc, Wo, bo, out);
}

// round 5
// speedup vs baseline: 1.1219x; 1.1219x over previous
#include <cuda_runtime.h>
#include <cuda_fp16.h>
#include <cstdint>

#define NV 50000
#define NE 1250000
#define DD 64

// ---------------- scratch (device globals: no runtime allocation allowed) ----
__device__ float  g_h[(size_t)NV * DD];        // node projection h = nf@Wn + bn
__device__ __half g_msg[(size_t)NE * DD];      // messages, stored in dst-sorted (CSR) order
__device__ int    g_rank[NE];                  // rank of edge within its dst bucket
__device__ int    g_cnt[NV];                   // histogram
__device__ int    g_off[NV + 1];               // CSR offsets
__device__ int    g_bsum[64];                  // scan block sums

// ---------------- helpers ---------------------------------------------------
__device__ __forceinline__ float sspf(float x) {
    // shifted softplus: log(1+e^x) - log(2), numerically stable
    return fmaxf(x, 0.f) + log1pf(expf(-fabsf(x))) - 0.69314718055994531f;
}

// fp16 mma m16n8k16, fp32 accumulate
__device__ __forceinline__ void mma_f16(float c[4], unsigned a0, unsigned a1,
                                        unsigned a2, unsigned a3,
                                        unsigned b0, unsigned b1) {
    asm("mma.sync.aligned.m16n8k16.row.col.f32.f16.f16.f32 "
        "{%0,%1,%2,%3}, {%4,%5,%6,%7}, {%8,%9}, {%0,%1,%2,%3};"
        : "+f"(c[0]), "+f"(c[1]), "+f"(c[2]), "+f"(c[3])
        : "r"(a0), "r"(a1), "r"(a2), "r"(a3), "r"(b0), "r"(b1));
}

// Pack 64x64 row-major W into per-lane m16n8k16 B-fragment order (fp16):
// Wp[((ks*8+nt)*32 + lane)*2 + j] = half2( W[kb][n], W[kb+1][n] )
//   kb = ks*16 + (lane&3)*2 + j*8 ; n = nt*8 + (lane>>2)
__device__ __forceinline__ void packW(const float* __restrict__ W, unsigned* Wp,
                                      int tid, int nthr) {
    for (int idx = tid; idx < 2048; idx += nthr) {
        int j    = idx & 1;
        int lane = (idx >> 1) & 31;
        int nt   = (idx >> 6) & 7;
        int ks   = idx >> 9;                  // 0..3
        int g = lane >> 2, t4 = lane & 3;
        int kb = ks * 16 + t4 * 2 + j * 8;
        int n  = nt * 8 + g;
        __half2 v = __floats2half2_rn(W[kb * DD + n], W[(kb + 1) * DD + n]);
        Wp[idx] = *(unsigned*)&v;
    }
}

// [128,64] @ [64,64] per block (A fp16 in smem, W pre-packed fragments).
// 8 warps x 16 rows, acc[nt][0..3] per thread.
__device__ __forceinline__ void gemm_tile(const __half (*As)[72],
                                          const unsigned* __restrict__ Wp,
                                          float acc[8][4], int wr, int gid,
                                          int tig, int lane) {
    #pragma unroll
    for (int ks = 0; ks < 4; ks++) {
        int k0 = ks * 16 + tig * 2;
        unsigned a0 = *(const unsigned*)&As[wr + gid    ][k0];
        unsigned a1 = *(const unsigned*)&As[wr + gid + 8][k0];
        unsigned a2 = *(const unsigned*)&As[wr + gid    ][k0 + 8];
        unsigned a3 = *(const unsigned*)&As[wr + gid + 8][k0 + 8];
        #pragma unroll
        for (int nt = 0; nt < 8; nt++) {
            uint2 b = ((const uint2*)Wp)[(ks * 8 + nt) * 32 + lane];
            mma_f16(acc[nt], a0, a1, a2, a3, b.x, b.y);
        }
    }
}

// ---------------- CSR build -------------------------------------------------
__global__ void zero_cnt_kernel() {
    int i = blockIdx.x * blockDim.x + threadIdx.x;
    if (i < NV) g_cnt[i] = 0;
}
__global__ void hist_kernel(const int* __restrict__ dst) {
    int e = blockIdx.x * blockDim.x + threadIdx.x;
    if (e < NE) g_rank[e] = atomicAdd(&g_cnt[dst[e]], 1);
}
__global__ void scan1_kernel() {
    __shared__ int ws[32];
    int t = threadIdx.x, b = blockIdx.x;
    int i = b * 1024 + t;
    int x = (i < NV) ? g_cnt[i] : 0;
    int incl = x;
    #pragma unroll
    for (int o = 1; o < 32; o <<= 1) {
        int n = __shfl_up_sync(0xffffffffu, incl, o);
        if ((t & 31) >= o) incl += n;
    }
    if ((t & 31) == 31) ws[t >> 5] = incl;
    __syncthreads();
    if (t < 32) {
        int v = ws[t];
        int iv = v;
        #pragma unroll
        for (int o = 1; o < 32; o <<= 1) {
            int n = __shfl_up_sync(0xffffffffu, iv, o);
            if (t >= o) iv += n;
        }
        ws[t] = iv - v;  // exclusive warp prefix
    }
    __syncthreads();
    int excl = ws[t >> 5] + incl - x;
    if (i < NV) g_off[i] = excl;
    if (t == 1023) g_bsum[b] = excl + x;
}
__global__ void scan2_kernel() {
    int run = 0;
    const int nb = (NV + 1023) / 1024;
    for (int b = 0; b < nb; b++) {
        int v = g_bsum[b];
        g_bsum[b] = run;
        run += v;
    }
}
__global__ void scan3_kernel() {
    int t = threadIdx.x, b = blockIdx.x;
    int i = b * 1024 + t;
    if (i < NV) g_off[i] += g_bsum[b];
    if (i == 0) g_off[NV] = NE;
}

// ---------------- h = node_feats @ Wn + bn ----------------------------------
struct HSmem {
    __half As[128][72];
    unsigned Wp[2048];
    float bs[64];
};
__global__ void __launch_bounds__(256, 2)
h_kernel(const float* __restrict__ nf, const float* __restrict__ Wn,
         const float* __restrict__ bn) {
    extern __shared__ char smraw[];
    HSmem& sm = *reinterpret_cast<HSmem*>(smraw);
    int tid = threadIdx.x, lane = tid & 31, warp = tid >> 5;
    int gid = lane >> 2, tig = lane & 3, wr = warp * 16;
    packW(Wn, sm.Wp, tid, 256);
    if (tid < 64) sm.bs[tid] = bn[tid];
    int base = blockIdx.x * 128;
    int rows = min(128, NV - base);
    #pragma unroll
    for (int j = 0; j < 8; j++) {
        int f4 = tid + j * 256;
        int r = f4 >> 4, c4 = f4 & 15;
        float4 v = (r < rows) ? ((const float4*)(nf + (size_t)(base + r) * DD))[c4]
                              : make_float4(0.f, 0.f, 0.f, 0.f);
        __half2 h0 = __floats2half2_rn(v.x, v.y);
        __half2 h1 = __floats2half2_rn(v.z, v.w);
        *(uint2*)&sm.As[r][c4 * 4] = make_uint2(*(unsigned*)&h0, *(unsigned*)&h1);
    }
    __syncthreads();
    float acc[8][4];
    #pragma unroll
    for (int i = 0; i < 8; i++)
        #pragma unroll
        for (int j = 0; j < 4; j++) acc[i][j] = 0.f;
    gemm_tile(sm.As, sm.Wp, acc, wr, gid, tig, lane);
    #pragma unroll
    for (int nt = 0; nt < 8; nt++) {
        int c0 = nt * 8 + tig * 2;
        float b0 = sm.bs[c0], b1 = sm.bs[c0 + 1];
        int r0 = wr + gid, r1 = wr + gid + 8;
        if (r0 < rows)
            *(float2*)(g_h + (size_t)(base + r0) * DD + c0) =
                make_float2(acc[nt][0] + b0, acc[nt][1] + b1);
        if (r1 < rows)
            *(float2*)(g_h + (size_t)(base + r1) * DD + c0) =
                make_float2(acc[nt][2] + b0, acc[nt][3] + b1);
    }
}

// ---------------- edge kernel: MLP + gather-modulate + CSR scatter-write ----
struct EdgeSmem {
    __half As[128][72];    // fp16 edge tile / intermediate / fp16 msg staging
    float Hs[128][68];     // gathered h rows (fp32)
    unsigned Wp1[2048];
    unsigned Wp2[2048];
    float b1s[64], b2s[64];
    int srcS[128];
    int slotS[128];
};
__global__ void __launch_bounds__(256, 2)
edge_kernel(const float* __restrict__ ef, const int* __restrict__ src,
            const int* __restrict__ dst, const float* __restrict__ We1,
            const float* __restrict__ be1, const float* __restrict__ We2,
            const float* __restrict__ be2) {
    extern __shared__ char smraw[];
    EdgeSmem& sm = *reinterpret_cast<EdgeSmem*>(smraw);
    const int tid = threadIdx.x, lane = tid & 31, warp = tid >> 5;
    const int gid = lane >> 2, tig = lane & 3, wr = warp * 16;

    packW(We1, sm.Wp1, tid, 256);
    packW(We2, sm.Wp2, tid, 256);
    if (tid < 64) { sm.b1s[tid] = be1[tid]; sm.b2s[tid] = be2[tid]; }

    const int numTiles = (NE + 127) / 128;
    for (int tile = blockIdx.x; tile < numTiles; tile += gridDim.x) {
        const int base = tile * 128;
        const int rows = min(128, NE - base);
        __syncthreads();  // prev-iter readers done; Wp ready (first iter)

        if (tid < 128) {
            int r = tid;
            if (r < rows) {
                sm.srcS[r]  = src[base + r];
                sm.slotS[r] = g_off[dst[base + r]] + g_rank[base + r];
            }
        }
        #pragma unroll
        for (int j = 0; j < 8; j++) {
            int f4 = tid + j * 256;
            int r = f4 >> 4, c4 = f4 & 15;
            float4 v = (r < rows)
                           ? ((const float4*)(ef + (size_t)(base + r) * DD))[c4]
                           : make_float4(0.f, 0.f, 0.f, 0.f);
            __half2 h0 = __floats2half2_rn(v.x, v.y);
            __half2 h1 = __floats2half2_rn(v.z, v.w);
            *(uint2*)&sm.As[r][c4 * 4] = make_uint2(*(unsigned*)&h0, *(unsigned*)&h1);
        }
        __syncthreads();

        // gather h[src] rows (random 256B reads, mostly L2 hits; hidden by MMA)
        #pragma unroll
        for (int j = 0; j < 8; j++) {
            int f4 = tid + j * 256;
            int r = f4 >> 4, c4 = f4 & 15;
            if (r < rows) {
                int s = sm.srcS[r];
                *(float4*)&sm.Hs[r][c4 * 4] =
                    ((const float4*)(g_h + (size_t)s * DD))[c4];
            }
        }

        float acc[8][4];
        #pragma unroll
        for (int i = 0; i < 8; i++)
            #pragma unroll
            for (int j = 0; j < 4; j++) acc[i][j] = 0.f;
        gemm_tile(sm.As, sm.Wp1, acc, wr, gid, tig, lane);
        __syncthreads();

        // ssp(x + b1) -> back into As (fp16)
        #pragma unroll
        for (int nt = 0; nt < 8; nt++) {
            int c0 = nt * 8 + tig * 2;
            float b0 = sm.b1s[c0], b1 = sm.b1s[c0 + 1];
            __half2 v0 = __floats2half2_rn(sspf(acc[nt][0] + b0), sspf(acc[nt][1] + b1));
            __half2 v1 = __floats2half2_rn(sspf(acc[nt][2] + b0), sspf(acc[nt][3] + b1));
            *(__half2*)&sm.As[wr + gid    ][c0] = v0;
            *(__half2*)&sm.As[wr + gid + 8][c0] = v1;
        }
        __syncthreads();

        #pragma unroll
        for (int i = 0; i < 8; i++)
            #pragma unroll
            for (int j = 0; j < 4; j++) acc[i][j] = 0.f;
        gemm_tile(sm.As, sm.Wp2, acc, wr, gid, tig, lane);
        __syncthreads();  // all warps done reading As before staging msg in it

        // f = ssp(x + b2); msg = f * h; stage as fp16 (reuse As, stride 72)
        __half* MsgS = (__half*)&sm.As[0][0];
        #pragma unroll
        for (int nt = 0; nt < 8; nt++) {
            int c0 = nt * 8 + tig * 2;
            float b0 = sm.b2s[c0], b1 = sm.b2s[c0 + 1];
            float2 h0 = *(const float2*)&sm.Hs[wr + gid    ][c0];
            float2 h1 = *(const float2*)&sm.Hs[wr + gid + 8][c0];
            float m0 = sspf(acc[nt][0] + b0) * h0.x;
            float m1 = sspf(acc[nt][1] + b1) * h0.y;
            float m2 = sspf(acc[nt][2] + b0) * h1.x;
            float m3 = sspf(acc[nt][3] + b1) * h1.y;
            *(__half2*)&MsgS[(wr + gid    ) * 72 + c0] = __floats2half2_rn(m0, m1);
            *(__half2*)&MsgS[(wr + gid + 8) * 72 + c0] = __floats2half2_rn(m2, m3);
        }
        __syncthreads();

        // scatter whole 128B rows to their CSR slot (coalesced 64B per thread)
        {
            int r = tid >> 1, part = tid & 1;
            if (r < rows) {
                int slot = sm.slotS[r];
                const uint4* sp = (const uint4*)&MsgS[r * 72 + part * 32];
                uint4* dp = (uint4*)(g_msg + (size_t)slot * DD + part * 32);
                #pragma unroll
                for (int i = 0; i < 4; i++) dp[i] = sp[i];
            }
        }
    }
}

// ---------------- node kernel: segment-sum + ssp(agg@Wc+bc)@Wo+bo -----------
struct NodeSmem {
    float Wc[64][64];
    float Wo[64][64];
    float agg[16][64];
    float bcs[64], bos[64];
};
__global__ void __launch_bounds__(512, 2)
node_kernel(const float* __restrict__ Wc, const float* __restrict__ bc,
            const float* __restrict__ Wo, const float* __restrict__ bo,
            float* __restrict__ out) {
    extern __shared__ char smraw[];
    NodeSmem& sm = *reinterpret_cast<NodeSmem*>(smraw);
    int tid = threadIdx.x, lane = tid & 31, warp = tid >> 5;  // 16 warps
    for (int i = tid; i < 4096; i += 512) ((float*)sm.Wc)[i] = Wc[i];
    for (int i = tid; i < 4096; i += 512) ((float*)sm.Wo)[i] = Wo[i];
    if (tid < 64) { sm.bcs[tid] = bc[tid]; sm.bos[tid] = bo[tid]; }
    __syncthreads();

    int v = blockIdx.x * 16 + warp;  // NV = 3125*16 exactly
    int s0 = g_off[v], s1 = g_off[v + 1];
    float a0 = 0.f, a1 = 0.f;  // cols 2*lane, 2*lane+1
    const unsigned* mp = (const unsigned*)g_msg;
    for (int s = s0; s < s1; s++) {
        unsigned u = mp[(size_t)s * 32 + lane];  // 128B coalesced per warp
        float2 f = __half22float2(*(__half2*)&u);
        a0 += f.x;
        a1 += f.y;
    }
    sm.agg[warp][2 * lane]     = a0;
    sm.agg[warp][2 * lane + 1] = a1;
    __syncwarp();

    float o0 = sm.bcs[2 * lane], o1 = sm.bcs[2 * lane + 1];
    #pragma unroll 8
    for (int k = 0; k < 64; k++) {
        float av = sm.agg[warp][k];
        float2 w = *(const float2*)&sm.Wc[k][2 * lane];
        o0 += av * w.x;
        o1 += av * w.y;
    }
    o0 = sspf(o0);
    o1 = sspf(o1);
    __syncwarp();
    sm.agg[warp][2 * lane]     = o0;
    sm.agg[warp][2 * lane + 1] = o1;
    __syncwarp();

    float r0 = sm.bos[2 * lane], r1 = sm.bos[2 * lane + 1];
    #pragma unroll 8
    for (int k = 0; k < 64; k++) {
        float tv = sm.agg[warp][k];
        float2 w = *(const float2*)&sm.Wo[k][2 * lane];
        r0 += tv * w.x;
        r1 += tv * w.y;
    }
    *(float2*)(out + (size_t)v * DD + 2 * lane) = make_float2(r0, r1);
}

// ---------------- launch ----------------------------------------------------
extern "C" void kernel_launch(void* const* d_in, const int* in_sizes, int n_in,
                              void* d_out, int out_size) {
    const float* nf  = (const float*)d_in[0];
    const float* ef  = (const float*)d_in[1];
    const int*   src = (const int*)d_in[2];
    const int*   dst = (const int*)d_in[3];
    const float* We1 = (const float*)d_in[4];
    const float* be1 = (const float*)d_in[5];
    const float* We2 = (const float*)d_in[6];
    const float* be2 = (const float*)d_in[7];
    const float* Wn  = (const float*)d_in[8];
    const float* bn  = (const float*)d_in[9];
    const float* Wc  = (const float*)d_in[10];
    const float* bc  = (const float*)d_in[11];
    const float* Wo  = (const float*)d_in[12];
    const float* bo  = (const float*)d_in[13];
    float* out = (float*)d_out;

    cudaFuncSetAttribute(edge_kernel, cudaFuncAttributeMaxDynamicSharedMemorySize,
                         (int)sizeof(EdgeSmem));
    cudaFuncSetAttribute(h_kernel, cudaFuncAttributeMaxDynamicSharedMemorySize,
                         (int)sizeof(HSmem));
    cudaFuncSetAttribute(node_kernel, cudaFuncAttributeMaxDynamicSharedMemorySize,
                         (int)sizeof(NodeSmem));

    const int scanBlocks = (NV + 1023) / 1024;  // 49
    zero_cnt_kernel<<<scanBlocks, 1024>>>();
    hist_kernel<<<(NE + 255) / 256, 256>>>(dst);
    scan1_kernel<<<scanBlocks, 1024>>>();
    scan2_kernel<<<1, 1>>>();
    scan3_kernel<<<scanBlocks, 1024>>>();
    h_kernel<<<(NV + 127) / 128, 256, sizeof(HSmem)>>>(nf, Wn, bn);
    edge_kernel<<<296, 256, sizeof(EdgeSmem)>>>(ef, src, dst, We1, be1, We2, be2);
    node_kernel<<<NV / 16, 512, sizeof(NodeSmem)>>>(Wc, bc, Wo, bo, out);
}

// round 7
// speedup vs baseline: 1.4875x; 1.3259x over previous
#include <cuda_runtime.h>
#include <cuda_fp16.h>
#include <cstdint>

#define NV 50000
#define NE 1250000
#define DD 64

// ---------------- scratch (device globals: no runtime allocation allowed) ----
__device__ float  g_h[(size_t)NV * DD];        // node projection h = nf@Wn + bn
__device__ __half g_msg[(size_t)NE * DD];      // messages, stored in dst-sorted (CSR) order
__device__ int    g_rank[NE];                  // rank of edge within its dst bucket
__device__ int    g_cnt[NV];                   // histogram (zero at entry: .bss on call 1,
                                               //  re-zeroed by trailing kernel every call)
__device__ int    g_off[NV + 1];               // CSR offsets

// ---------------- helpers ---------------------------------------------------
__device__ __forceinline__ float sspf(float x) {
    // shifted softplus via fast-math MUFU: log(1+e^x) - log(2)
    // arg of __logf is in (1,2] -> best-accuracy region; abs err ~1e-6
    return fmaxf(x, 0.f) + __logf(1.f + __expf(-fabsf(x))) - 0.69314718055994531f;
}

// fp16 mma m16n8k16, fp32 accumulate
__device__ __forceinline__ void mma_f16(float c[4], unsigned a0, unsigned a1,
                                        unsigned a2, unsigned a3,
                                        unsigned b0, unsigned b1) {
    asm("mma.sync.aligned.m16n8k16.row.col.f32.f16.f16.f32 "
        "{%0,%1,%2,%3}, {%4,%5,%6,%7}, {%8,%9}, {%0,%1,%2,%3};"
        : "+f"(c[0]), "+f"(c[1]), "+f"(c[2]), "+f"(c[3])
        : "r"(a0), "r"(a1), "r"(a2), "r"(a3), "r"(b0), "r"(b1));
}

// Pack 64x64 row-major W into per-lane m16n8k16 B-fragment order (fp16).
__device__ __forceinline__ void packW(const float* __restrict__ W, unsigned* Wp,
                                      int tid, int nthr) {
    for (int idx = tid; idx < 2048; idx += nthr) {
        int j    = idx & 1;
        int lane = (idx >> 1) & 31;
        int nt   = (idx >> 6) & 7;
        int ks   = idx >> 9;                  // 0..3
        int g = lane >> 2, t4 = lane & 3;
        int kb = ks * 16 + t4 * 2 + j * 8;
        int n  = nt * 8 + g;
        __half2 v = __floats2half2_rn(W[kb * DD + n], W[(kb + 1) * DD + n]);
        Wp[idx] = *(unsigned*)&v;
    }
}

// [128,64] @ [64,64] per block (A fp16 in smem, W pre-packed fragments).
__device__ __forceinline__ void gemm_tile(const __half (*As)[72],
                                          const unsigned* __restrict__ Wp,
                                          float acc[8][4], int wr, int gid,
                                          int tig, int lane) {
    #pragma unroll
    for (int ks = 0; ks < 4; ks++) {
        int k0 = ks * 16 + tig * 2;
        unsigned a0 = *(const unsigned*)&As[wr + gid    ][k0];
        unsigned a1 = *(const unsigned*)&As[wr + gid + 8][k0];
        unsigned a2 = *(const unsigned*)&As[wr + gid    ][k0 + 8];
        unsigned a3 = *(const unsigned*)&As[wr + gid + 8][k0 + 8];
        #pragma unroll
        for (int nt = 0; nt < 8; nt++) {
            uint2 b = ((const uint2*)Wp)[(ks * 8 + nt) * 32 + lane];
            mma_f16(acc[nt], a0, a1, a2, a3, b.x, b.y);
        }
    }
}

// ---------------- CSR build -------------------------------------------------
__global__ void hist_kernel(const int* __restrict__ dst) {
    int e = blockIdx.x * blockDim.x + threadIdx.x;
    if (e < NE) g_rank[e] = atomicAdd(&g_cnt[dst[e]], 1);
}

// single-block exclusive scan of g_cnt[0..NV) -> g_off
__global__ void scan_all_kernel() {
    __shared__ int ws[32];
    __shared__ int tshare;
    int t = threadIdx.x, lane = t & 31, wid = t >> 5;
    int carry = 0;
    const int nchunks = (NV + 1023) / 1024;  // 49
    for (int c = 0; c < nchunks; c++) {
        int i = c * 1024 + t;
        int x = (i < NV) ? g_cnt[i] : 0;
        int incl = x;
        #pragma unroll
        for (int o = 1; o < 32; o <<= 1) {
            int n = __shfl_up_sync(0xffffffffu, incl, o);
            if (lane >= o) incl += n;
        }
        if (lane == 31) ws[wid] = incl;
        __syncthreads();
        if (t < 32) {
            int v = ws[t];
            int iv = v;
            #pragma unroll
            for (int o = 1; o < 32; o <<= 1) {
                int n = __shfl_up_sync(0xffffffffu, iv, o);
                if (t >= o) iv += n;
            }
            ws[t] = iv - v;  // exclusive warp prefix
        }
        __syncthreads();
        int excl = ws[wid] + incl - x;
        if (i < NV) g_off[i] = carry + excl;
        if (t == 1023) tshare = excl + x;
        __syncthreads();
        carry += tshare;
        __syncthreads();
    }
    if (t == 0) g_off[NV] = NE;
}

__global__ void zero_cnt_kernel() {  // runs LAST: re-zero for next invocation
    int i = blockIdx.x * blockDim.x + threadIdx.x;
    if (i < NV) g_cnt[i] = 0;
}

// ---------------- h = node_feats @ Wn + bn ----------------------------------
struct HSmem {
    __half As[128][72];
    unsigned Wp[2048];
    float bs[64];
};
__global__ void __launch_bounds__(256, 2)
h_kernel(const float* __restrict__ nf, const float* __restrict__ Wn,
         const float* __restrict__ bn) {
    extern __shared__ char smraw[];
    HSmem& sm = *reinterpret_cast<HSmem*>(smraw);
    int tid = threadIdx.x, lane = tid & 31, warp = tid >> 5;
    int gid = lane >> 2, tig = lane & 3, wr = warp * 16;
    packW(Wn, sm.Wp, tid, 256);
    if (tid < 64) sm.bs[tid] = bn[tid];
    int base = blockIdx.x * 128;
    int rows = min(128, NV - base);
    #pragma unroll
    for (int j = 0; j < 8; j++) {
        int f4 = tid + j * 256;
        int r = f4 >> 4, c4 = f4 & 15;
        float4 v = (r < rows) ? ((const float4*)(nf + (size_t)(base + r) * DD))[c4]
                              : make_float4(0.f, 0.f, 0.f, 0.f);
        __half2 h0 = __floats2half2_rn(v.x, v.y);
        __half2 h1 = __floats2half2_rn(v.z, v.w);
        *(uint2*)&sm.As[r][c4 * 4] = make_uint2(*(unsigned*)&h0, *(unsigned*)&h1);
    }
    __syncthreads();
    float acc[8][4];
    #pragma unroll
    for (int i = 0; i < 8; i++)
        #pragma unroll
        for (int j = 0; j < 4; j++) acc[i][j] = 0.f;
    gemm_tile(sm.As, sm.Wp, acc, wr, gid, tig, lane);
    #pragma unroll
    for (int nt = 0; nt < 8; nt++) {
        int c0 = nt * 8 + tig * 2;
        float b0 = sm.bs[c0], b1 = sm.bs[c0 + 1];
        int r0 = wr + gid, r1 = wr + gid + 8;
        if (r0 < rows)
            *(float2*)(g_h + (size_t)(base + r0) * DD + c0) =
                make_float2(acc[nt][0] + b0, acc[nt][1] + b1);
        if (r1 < rows)
            *(float2*)(g_h + (size_t)(base + r1) * DD + c0) =
                make_float2(acc[nt][2] + b0, acc[nt][3] + b1);
    }
}

// ---------------- edge kernel: MLP + gather-modulate + CSR scatter-write ----
struct EdgeSmem {
    __half As[128][72];    // fp16 edge tile / intermediate / fp16 msg staging
    unsigned Wp1[2048];
    unsigned Wp2[2048];
    float b1s[64], b2s[64];
    int slotS[128];
};
__global__ void __launch_bounds__(256, 3)
edge_kernel(const float* __restrict__ ef, const int* __restrict__ src,
            const int* __restrict__ dst, const float* __restrict__ We1,
            const float* __restrict__ be1, const float* __restrict__ We2,
            const float* __restrict__ be2) {
    extern __shared__ char smraw[];
    EdgeSmem& sm = *reinterpret_cast<EdgeSmem*>(smraw);
    const int tid = threadIdx.x, lane = tid & 31, warp = tid >> 5;
    const int gid = lane >> 2, tig = lane & 3, wr = warp * 16;
    const int r0 = wr + gid, r1 = r0 + 8;  // the two rows this thread owns

    packW(We1, sm.Wp1, tid, 256);
    packW(We2, sm.Wp2, tid, 256);
    if (tid < 64) { sm.b1s[tid] = be1[tid]; sm.b2s[tid] = be2[tid]; }

    const int numTiles = (NE + 127) / 128;
    for (int tile = blockIdx.x; tile < numTiles; tile += gridDim.x) {
        const int base = tile * 128;
        const int rows = min(128, NE - base);
        __syncthreads();  // prev-iter readers done; Wp ready (first iter)

        if (tid < 128 && tid < rows)
            sm.slotS[tid] = g_off[dst[base + tid]] + g_rank[base + tid];

        #pragma unroll
        for (int j = 0; j < 8; j++) {
            int f4 = tid + j * 256;
            int r = f4 >> 4, c4 = f4 & 15;
            float4 v = (r < rows)
                           ? ((const float4*)(ef + (size_t)(base + r) * DD))[c4]
                           : make_float4(0.f, 0.f, 0.f, 0.f);
            __half2 h0 = __floats2half2_rn(v.x, v.y);
            __half2 h1 = __floats2half2_rn(v.z, v.w);
            *(uint2*)&sm.As[r][c4 * 4] = make_uint2(*(unsigned*)&h0, *(unsigned*)&h1);
        }
        __syncthreads();

        float acc[8][4];
        #pragma unroll
        for (int i = 0; i < 8; i++)
            #pragma unroll
            for (int j = 0; j < 4; j++) acc[i][j] = 0.f;
        gemm_tile(sm.As, sm.Wp1, acc, wr, gid, tig, lane);
        __syncthreads();

        // ssp(x + b1) -> back into As (fp16)
        #pragma unroll
        for (int nt = 0; nt < 8; nt++) {
            int c0 = nt * 8 + tig * 2;
            float b0 = sm.b1s[c0], b1 = sm.b1s[c0 + 1];
            __half2 v0 = __floats2half2_rn(sspf(acc[nt][0] + b0), sspf(acc[nt][1] + b1));
            __half2 v1 = __floats2half2_rn(sspf(acc[nt][2] + b0), sspf(acc[nt][3] + b1));
            *(__half2*)&sm.As[wr + gid    ][c0] = v0;
            *(__half2*)&sm.As[wr + gid + 8][c0] = v1;
        }
        __syncthreads();

        // issue h[src] gathers for this thread's rows/cols; scoreboard lets
        // these fly while the MMAs below execute (no dependency)
        int s0 = (r0 < rows) ? src[base + r0] : 0;
        int s1 = (r1 < rows) ? src[base + r1] : 0;
        const float2* h0p = (const float2*)(g_h + (size_t)s0 * DD);
        const float2* h1p = (const float2*)(g_h + (size_t)s1 * DD);
        float2 hv0[8], hv1[8];
        #pragma unroll
        for (int nt = 0; nt < 8; nt++) {
            hv0[nt] = h0p[nt * 4 + tig];
            hv1[nt] = h1p[nt * 4 + tig];
        }

        #pragma unroll
        for (int i = 0; i < 8; i++)
            #pragma unroll
            for (int j = 0; j < 4; j++) acc[i][j] = 0.f;
        gemm_tile(sm.As, sm.Wp2, acc, wr, gid, tig, lane);
        __syncthreads();  // all warps done reading As before staging msg in it

        // f = ssp(x + b2); msg = f * h; stage as fp16 (reuse As, stride 72)
        __half* MsgS = (__half*)&sm.As[0][0];
        #pragma unroll
        for (int nt = 0; nt < 8; nt++) {
            int c0 = nt * 8 + tig * 2;
            float b0 = sm.b2s[c0], b1 = sm.b2s[c0 + 1];
            float m0 = sspf(acc[nt][0] + b0) * hv0[nt].x;
            float m1 = sspf(acc[nt][1] + b1) * hv0[nt].y;
            float m2 = sspf(acc[nt][2] + b0) * hv1[nt].x;
            float m3 = sspf(acc[nt][3] + b1) * hv1[nt].y;
            *(__half2*)&MsgS[r0 * 72 + c0] = __floats2half2_rn(m0, m1);
            *(__half2*)&MsgS[r1 * 72 + c0] = __floats2half2_rn(m2, m3);
        }
        __syncthreads();

        // scatter whole 128B rows to their CSR slot (coalesced 64B per thread)
        {
            int r = tid >> 1, part = tid & 1;
            if (r < rows) {
                int slot = sm.slotS[r];
                const uint4* sp = (const uint4*)&MsgS[r * 72 + part * 32];
                uint4* dp = (uint4*)(g_msg + (size_t)slot * DD + part * 32);
                #pragma unroll
                for (int i = 0; i < 4; i++) dp[i] = sp[i];
            }
        }
    }
}

// ---------------- node kernel: segment-sum + ssp(agg@Wc+bc)@Wo+bo -----------
struct NodeSmem {
    float Wc[64][64];
    float Wo[64][64];
    float agg[16][64];
    float bcs[64], bos[64];
};
__global__ void __launch_bounds__(512, 2)
node_kernel(const float* __restrict__ Wc, const float* __restrict__ bc,
            const float* __restrict__ Wo, const float* __restrict__ bo,
            float* __restrict__ out) {
    extern __shared__ char smraw[];
    NodeSmem& sm = *reinterpret_cast<NodeSmem*>(smraw);
    int tid = threadIdx.x, lane = tid & 31, warp = tid >> 5;  // 16 warps
    for (int i = tid; i < 4096; i += 512) ((float*)sm.Wc)[i] = Wc[i];
    for (int i = tid; i < 4096; i += 512) ((float*)sm.Wo)[i] = Wo[i];
    if (tid < 64) { sm.bcs[tid] = bc[tid]; sm.bos[tid] = bo[tid]; }
    __syncthreads();

    int v = blockIdx.x * 16 + warp;  // NV = 3125*16 exactly
    int s0 = g_off[v], s1 = g_off[v + 1];
    float a0 = 0.f, a1 = 0.f;  // cols 2*lane, 2*lane+1
    const unsigned* mp = (const unsigned*)g_msg;
    #pragma unroll 4
    for (int s = s0; s < s1; s++) {
        unsigned u = mp[(size_t)s * 32 + lane];  // 128B coalesced per warp
        float2 f = __half22float2(*(__half2*)&u);
        a0 += f.x;
        a1 += f.y;
    }
    sm.agg[warp][2 * lane]     = a0;
    sm.agg[warp][2 * lane + 1] = a1;
    __syncwarp();

    float o0 = sm.bcs[2 * lane], o1 = sm.bcs[2 * lane + 1];
    #pragma unroll 8
    for (int k = 0; k < 64; k++) {
        float av = sm.agg[warp][k];
        float2 w = *(const float2*)&sm.Wc[k][2 * lane];
        o0 += av * w.x;
        o1 += av * w.y;
    }
    o0 = sspf(o0);
    o1 = sspf(o1);
    __syncwarp();
    sm.agg[warp][2 * lane]     = o0;
    sm.agg[warp][2 * lane + 1] = o1;
    __syncwarp();

    float r0 = sm.bos[2 * lane], r1 = sm.bos[2 * lane + 1];
    #pragma unroll 8
    for (int k = 0; k < 64; k++) {
        float tv = sm.agg[warp][k];
        float2 w = *(const float2*)&sm.Wo[k][2 * lane];
        r0 += tv * w.x;
        r1 += tv * w.y;
    }
    *(float2*)(out + (size_t)v * DD + 2 * lane) = make_float2(r0, r1);
}

// ---------------- launch ----------------------------------------------------
extern "C" void kernel_launch(void* const* d_in, const int* in_sizes, int n_in,
                              void* d_out, int out_size) {
    const float* nf  = (const float*)d_in[0];
    const float* ef  = (const float*)d_in[1];
    const int*   src = (const int*)d_in[2];
    const int*   dst = (const int*)d_in[3];
    const float* We1 = (const float*)d_in[4];
    const float* be1 = (const float*)d_in[5];
    const float* We2 = (const float*)d_in[6];
    const float* be2 = (const float*)d_in[7];
    const float* Wn  = (const float*)d_in[8];
    const float* bn  = (const float*)d_in[9];
    const float* Wc  = (const float*)d_in[10];
    const float* bc  = (const float*)d_in[11];
    const float* Wo  = (const float*)d_in[12];
    const float* bo  = (const float*)d_in[13];
    float* out = (float*)d_out;

    cudaFuncSetAttribute(edge_kernel, cudaFuncAttributeMaxDynamicSharedMemorySize,
                         (int)sizeof(EdgeSmem));
    cudaFuncSetAttribute(h_kernel, cudaFuncAttributeMaxDynamicSharedMemorySize,
                         (int)sizeof(HSmem));
    cudaFuncSetAttribute(node_kernel, cudaFuncAttributeMaxDynamicSharedMemorySize,
                         (int)sizeof(NodeSmem));

    // g_cnt is zero on entry (zero-init .bss on call 1; trailing zero_cnt_kernel
    // re-establishes the invariant for subsequent graph replays)
    hist_kernel<<<(NE + 255) / 256, 256>>>(dst);                    // launch 1
    scan_all_kernel<<<1, 1024>>>();                                 // launch 2
    h_kernel<<<(NV + 127) / 128, 256, sizeof(HSmem)>>>(nf, Wn, bn); // launch 3
    edge_kernel<<<444, 256, sizeof(EdgeSmem)>>>(ef, src, dst,       // launch 4
                                                We1, be1, We2, be2);
    node_kernel<<<NV / 16, 512, sizeof(NodeSmem)>>>(Wc, bc, Wo, bo, out); // 5
    zero_cnt_kernel<<<(NV + 1023) / 1024, 1024>>>();                // launch 6
}